// round 15
// baseline (speedup 1.0000x reference)
#include <cuda_runtime.h>
#include <cuda_fp16.h>
#include <cfloat>
#include <cstdint>

// Problem: x [65536, 256] fp32, codebook [1024, 256] fp32. Nearest code per row.
#define N_ROWS  65536
#define DIM     256
#define KCODES  1024
#define RN      128     // rows per CTA
#define CN      128     // codes per chunk
#define NCHUNK  (KCODES / CN)
#define KS      32      // dims per stage
#define NST     (DIM / KS)
#define NTHREADS 512
#define EPS     0.25f   // ~10 sigma of fp16 hh-only distance error; rescue is exact regardless

// smem layout (bytes). fp16 tiles: 128 rows x 32 dims x 2B = 8KB per region per buffer.
#define OFF_AH     0        // 2 x 8KB
#define OFF_BH     16384    // 2 x 8KB
#define OFF_SNORM  32768
#define OFF_SREDV  36864
#define OFF_SREDW  38912
#define OFF_SREDI  40960
#define OFF_SIDX   43008
#define SMEM_BYTES 43520
#define BUFSTRIDE  8192

__device__ float g_enorm[KCODES];
__device__ int   g_nflag;
__device__ int   g_list[N_ROWS];

__device__ __forceinline__ uint32_t smem_u32(const void* p) {
    uint32_t a;
    asm("{ .reg .u64 t; cvta.to.shared.u64 t, %1; cvt.u32.u64 %0, t; }" : "=r"(a) : "l"(p));
    return a;
}

// float4 -> packed fp16x2 pair (element order matches validated bf16 layout)
__device__ __forceinline__ uint2 f16_pack(float4 v) {
    uint2 h;
    asm("cvt.rn.f16x2.f32 %0, %1, %2;" : "=r"(h.x) : "f"(v.y), "f"(v.x));
    asm("cvt.rn.f16x2.f32 %0, %1, %2;" : "=r"(h.y) : "f"(v.w), "f"(v.z));
    return h;
}

__device__ __forceinline__ void ldm4(uint32_t* r, uint32_t addr) {
    asm volatile("ldmatrix.sync.aligned.m8n8.x4.shared.b16 {%0,%1,%2,%3}, [%4];"
                 : "=r"(r[0]), "=r"(r[1]), "=r"(r[2]), "=r"(r[3]) : "r"(addr));
}

__device__ __forceinline__ void mma16f(float* c, const uint32_t* a, uint32_t b0, uint32_t b1) {
    asm volatile(
        "mma.sync.aligned.m16n8k16.row.col.f32.f16.f16.f32 "
        "{%0,%1,%2,%3}, {%4,%5,%6,%7}, {%8,%9}, {%0,%1,%2,%3};"
        : "+f"(c[0]), "+f"(c[1]), "+f"(c[2]), "+f"(c[3])
        : "r"(a[0]), "r"(a[1]), "r"(a[2]), "r"(a[3]), "r"(b0), "r"(b1));
}

__global__ void enorm_kernel(const float* __restrict__ cb) {
    int code = blockIdx.x;
    int t = threadIdx.x;  // 64 threads, one float4 each
    if (code == 0 && t == 0) g_nflag = 0;    // reset rescue list every replay
    const float4* row = reinterpret_cast<const float4*>(cb + (size_t)code * DIM);
    float4 v = row[t];
    float s = v.x * v.x + v.y * v.y + v.z * v.z + v.w * v.w;
    #pragma unroll
    for (int o = 16; o > 0; o >>= 1) s += __shfl_down_sync(0xffffffffu, s, o);
    __shared__ float ws[2];
    if ((t & 31) == 0) ws[t >> 5] = s;
    __syncthreads();
    if (t == 0) g_enorm[code] = ws[0] + ws[1];
}

__global__ __launch_bounds__(NTHREADS, 1)
void vq_kernel(const float* __restrict__ x, const float* __restrict__ cb,
               float* __restrict__ outq, float* __restrict__ outidx, int has_idx)
{
    extern __shared__ char sm[];
    const uint32_t sb = smem_u32(sm);
    const int tid  = threadIdx.x;
    const int lane = tid & 31;
    const int wid  = tid >> 5;       // 0..15
    const int wm   = wid & 3;        // rows wm*32..+31
    const int wn   = wid >> 2;       // codes wn*32..+31 within 128-code chunk
    const int r0   = blockIdx.x * RN;

    float* snorm = (float*)(sm + OFF_SNORM);
    for (int i = tid; i < KCODES; i += NTHREADS) snorm[i] = g_enorm[i];

    // stage-load mapping: float4 f -> (row, quad q of 8 per 32-dim stage)
    // blocked 8x8-fp16 tile layout: tile(mb,kb) at (mb*4+kb)*128, within: (row&7)*16 + (q&1)*8
    const int f1 = tid, f2 = tid + 512;
    const int row1 = f1 >> 3, q1 = f1 & 7;
    const int row2 = f2 >> 3, q2 = f2 & 7;
    const uint32_t d1 = (uint32_t)(((row1 >> 3) * 4 + (q1 >> 1)) * 128 + (row1 & 7) * 16 + (q1 & 1) * 8);
    const uint32_t d2 = (uint32_t)(((row2 >> 3) * 4 + (q2 >> 1)) * 128 + (row2 & 7) * 16 + (q2 & 1) * 8);

    // ldmatrix lane offsets (fragment layout validated R6/R12/R14)
    const uint32_t aoff = ((lane >> 3) & 1) * 512 + (lane >> 4) * 128 + (lane & 7) * 16;
    const uint32_t boff = ((lane >> 3) & 1) * 128 + (lane >> 4) * 512 + (lane & 7) * 16;

    float minv[4], minw[4];
    int   mini[4];
    #pragma unroll
    for (int i = 0; i < 4; i++) { minv[i] = FLT_MAX; minw[i] = FLT_MAX; mini[i] = 0; }

    #pragma unroll 1
    for (int c = 0; c < NCHUNK; c++) {
        const int cbase = c * CN;
        float acc[2][4][4];
        #pragma unroll
        for (int mt = 0; mt < 2; mt++)
            #pragma unroll
            for (int nt = 0; nt < 4; nt++)
                #pragma unroll
                for (int q = 0; q < 4; q++) acc[mt][nt][q] = 0.0f;

        __syncthreads();

        // --- stage 0 load: LDG + fp16 pack + STS ---
        {
            const float4 a1 = *(const float4*)(x  + (size_t)(r0 + row1) * DIM + q1 * 4);
            const float4 a2 = *(const float4*)(x  + (size_t)(r0 + row2) * DIM + q2 * 4);
            const float4 b1 = *(const float4*)(cb + (size_t)(cbase + row1) * DIM + q1 * 4);
            const float4 b2 = *(const float4*)(cb + (size_t)(cbase + row2) * DIM + q2 * 4);
            *(uint2*)(sm + OFF_AH + d1) = f16_pack(a1);
            *(uint2*)(sm + OFF_AH + d2) = f16_pack(a2);
            *(uint2*)(sm + OFF_BH + d1) = f16_pack(b1);
            *(uint2*)(sm + OFF_BH + d2) = f16_pack(b2);
        }
        __syncthreads();

        int buf = 0;
        #pragma unroll 1
        for (int s = 0; s < NST; s++) {
            float4 pa1, pa2, pb1, pb2;
            if (s < NST - 1) {
                const int dd = (s + 1) * KS;
                pa1 = *(const float4*)(x  + (size_t)(r0 + row1) * DIM + dd + q1 * 4);
                pa2 = *(const float4*)(x  + (size_t)(r0 + row2) * DIM + dd + q2 * 4);
                pb1 = *(const float4*)(cb + (size_t)(cbase + row1) * DIM + dd + q1 * 4);
                pb2 = *(const float4*)(cb + (size_t)(cbase + row2) * DIM + dd + q2 * 4);
            }

            const uint32_t ahb = sb + OFF_AH + (uint32_t)buf * BUFSTRIDE;
            const uint32_t bhb = sb + OFF_BH + (uint32_t)buf * BUFSTRIDE;

            #pragma unroll
            for (int ks2 = 0; ks2 < 2; ks2++) {    // two k16 slices per 32-dim stage
                uint32_t ah[2][4], bh[2][4];
                #pragma unroll
                for (int mt = 0; mt < 2; mt++) {
                    const uint32_t tb = (uint32_t)((((wm * 4 + mt * 2) * 4) + ks2 * 2) * 128);
                    ldm4(ah[mt], ahb + tb + aoff);
                }
                #pragma unroll
                for (int np = 0; np < 2; np++) {
                    const uint32_t tb = (uint32_t)((((wn * 4 + np * 2) * 4) + ks2 * 2) * 128);
                    ldm4(bh[np], bhb + tb + boff);
                }
                // single fp16 product (hh), 8 MMAs, revisit distance 8
                #pragma unroll
                for (int np = 0; np < 2; np++)
                    #pragma unroll
                    for (int mt = 0; mt < 2; mt++) {
                        mma16f(acc[mt][np * 2],     ah[mt], bh[np][0], bh[np][1]);
                        mma16f(acc[mt][np * 2 + 1], ah[mt], bh[np][2], bh[np][3]);
                    }
            }

            if (s < NST - 1) {
                const int nb = buf ^ 1;
                *(uint2*)(sm + OFF_AH + nb * BUFSTRIDE + d1) = f16_pack(pa1);
                *(uint2*)(sm + OFF_AH + nb * BUFSTRIDE + d2) = f16_pack(pa2);
                *(uint2*)(sm + OFF_BH + nb * BUFSTRIDE + d1) = f16_pack(pb1);
                *(uint2*)(sm + OFF_BH + nb * BUFSTRIDE + d2) = f16_pack(pb2);
                __syncthreads();
                buf = nb;
            }
        }

        // --- chunk epilogue: dist = ||e||^2 - 2 x.e ; track best + second-best ---
        #pragma unroll
        for (int nt = 0; nt < 4; nt++) {
            const int code0 = cbase + wn * 32 + nt * 8 + 2 * (lane & 3);
            const float en0 = snorm[code0];
            const float en1 = snorm[code0 + 1];
            #pragma unroll
            for (int mt = 0; mt < 2; mt++) {
                const float* a = acc[mt][nt];
                const int s0 = mt * 2, s1 = mt * 2 + 1;
                float d;
                d = en0 - 2.0f * a[0];
                if (d < minv[s0]) { minw[s0] = minv[s0]; minv[s0] = d; mini[s0] = code0; }
                else if (d < minw[s0]) minw[s0] = d;
                d = en1 - 2.0f * a[1];
                if (d < minv[s0]) { minw[s0] = minv[s0]; minv[s0] = d; mini[s0] = code0 + 1; }
                else if (d < minw[s0]) minw[s0] = d;
                d = en0 - 2.0f * a[2];
                if (d < minv[s1]) { minw[s1] = minv[s1]; minv[s1] = d; mini[s1] = code0; }
                else if (d < minw[s1]) minw[s1] = d;
                d = en1 - 2.0f * a[3];
                if (d < minv[s1]) { minw[s1] = minv[s1]; minv[s1] = d; mini[s1] = code0 + 1; }
                else if (d < minw[s1]) minw[s1] = d;
            }
        }
    }

    // --- reduce (best, idx, second) across lane%4 group, then across 4 wn groups ---
    float* sredv = (float*)(sm + OFF_SREDV);
    float* sredw = (float*)(sm + OFF_SREDW);
    int*   sredi = (int*)(sm + OFF_SREDI);
    #pragma unroll
    for (int sl = 0; sl < 4; sl++) {
        float v = minv[sl], w = minw[sl];
        int   id = mini[sl];
        #pragma unroll
        for (int o = 1; o <= 2; o <<= 1) {
            const float ov = __shfl_xor_sync(0xffffffffu, v, o);
            const float ow = __shfl_xor_sync(0xffffffffu, w, o);
            const int   oi = __shfl_xor_sync(0xffffffffu, id, o);
            if (ov < v || (ov == v && oi < id)) { w = fminf(v, ow); v = ov; id = oi; }
            else                                 { w = fminf(ov, w); }
        }
        if ((lane & 3) == 0) {
            const int rowl = wm * 32 + (sl >> 1) * 16 + (sl & 1) * 8 + (lane >> 2);
            sredv[wn * 128 + rowl] = v;
            sredw[wn * 128 + rowl] = w;
            sredi[wn * 128 + rowl] = id;
        }
    }
    __syncthreads();
    int* sIdx = (int*)(sm + OFF_SIDX);
    if (tid < 128) {
        float v0 = sredv[tid], w0 = sredw[tid];
        int   i0 = sredi[tid];
        #pragma unroll
        for (int g = 1; g < 4; g++) {
            const float v1 = sredv[g * 128 + tid];
            const float w1 = sredw[g * 128 + tid];
            const int   i1 = sredi[g * 128 + tid];
            if (v1 < v0 || (v1 == v0 && i1 < i0)) { w0 = fminf(v0, w1); v0 = v1; i0 = i1; }
            else                                  { w0 = fminf(v1, w0); }
        }
        sIdx[tid] = i0;
        if (w0 - v0 < EPS) {
            const int p = atomicAdd(&g_nflag, 1);   // compacted rescue list
            g_list[p] = r0 + tid;
        }
    }
    __syncthreads();

    // --- gather e[idx] rows and write outputs ---
    const float4* cb4  = reinterpret_cast<const float4*>(cb);
    float4*       out4 = reinterpret_cast<float4*>(outq);
    #pragma unroll 4
    for (int f = tid; f < RN * DIM / 4; f += NTHREADS) {
        const int row  = f >> 6;
        const int cc   = f & 63;
        const int code = sIdx[row];
        out4[(size_t)(r0 + row) * (DIM / 4) + cc] = cb4[(size_t)code * (DIM / 4) + cc];
    }
    if (has_idx && tid < RN) outidx[r0 + tid] = (float)sIdx[tid];
}

// --- exact fp32 rescan for flagged rows (grid-strided over compacted list) ---
__global__ __launch_bounds__(256)
void rescan_kernel(const float* __restrict__ x, const float* __restrict__ cb,
                   float* __restrict__ outq, float* __restrict__ outidx, int has_idx)
{
    __shared__ float4 sx[DIM / 4];
    __shared__ float rv[256];
    __shared__ int   ri[256];
    const int tid = threadIdx.x;
    const int nflag = g_nflag;

    for (int it = blockIdx.x; it < nflag; it += gridDim.x) {
        const int row = g_list[it];
        if (tid < 64) sx[tid] = ((const float4*)(x + (size_t)row * DIM))[tid];
        __syncthreads();

        float best = FLT_MAX;
        int   bidx = 0;
        #pragma unroll 1
        for (int cc = 0; cc < 4; cc++) {
            const int code = tid + cc * 256;   // ascending per thread
            const float4* e4 = (const float4*)(cb + (size_t)code * DIM);
            float dot = 0.0f;
            #pragma unroll 8
            for (int i = 0; i < DIM / 4; i++) {
                const float4 ev = e4[i];
                const float4 xv = sx[i];
                dot = fmaf(xv.x, ev.x, dot);
                dot = fmaf(xv.y, ev.y, dot);
                dot = fmaf(xv.z, ev.z, dot);
                dot = fmaf(xv.w, ev.w, dot);
            }
            const float d = g_enorm[code] - 2.0f * dot;
            if (d < best) { best = d; bidx = code; }
        }
        rv[tid] = best; ri[tid] = bidx;
        __syncthreads();
        for (int o = 128; o > 0; o >>= 1) {
            if (tid < o) {
                const float v2 = rv[tid + o];
                const int   i2 = ri[tid + o];
                if (v2 < rv[tid] || (v2 == rv[tid] && i2 < ri[tid])) { rv[tid] = v2; ri[tid] = i2; }
            }
            __syncthreads();
        }
        const int widx = ri[0];
        if (tid < 64)
            ((float4*)(outq + (size_t)row * DIM))[tid] = ((const float4*)(cb + (size_t)widx * DIM))[tid];
        if (has_idx && tid == 0) outidx[row] = (float)widx;
        __syncthreads();
    }
}

extern "C" void kernel_launch(void* const* d_in, const int* in_sizes, int n_in,
                              void* d_out, int out_size) {
    const float* x  = (const float*)d_in[0];   // [65536, 256]
    const float* cb = (const float*)d_in[1];   // [1024, 256]
    float* outq = (float*)d_out;

    const int qElems = N_ROWS * DIM;
    const int has_idx = (out_size >= qElems + N_ROWS) ? 1 : 0;
    float* outidx = outq + qElems;

    cudaFuncSetAttribute(vq_kernel, cudaFuncAttributeMaxDynamicSharedMemorySize, SMEM_BYTES);

    enorm_kernel<<<KCODES, 64>>>(cb);
    vq_kernel<<<N_ROWS / RN, NTHREADS, SMEM_BYTES>>>(x, cb, outq, outidx, has_idx);
    rescan_kernel<<<1024, 256>>>(x, cb, outq, outidx, has_idx);
}

// round 16
// speedup vs baseline: 2.5753x; 2.5753x over previous
#include <cuda_runtime.h>
#include <cuda_bf16.h>
#include <cfloat>
#include <cstdint>

// Problem: x [65536, 256] fp32, codebook [1024, 256] fp32. Nearest code per row.
#define N_ROWS  65536
#define DIM     256
#define KCODES  1024
#define RN      128     // rows per CTA
#define CN      128     // codes per chunk
#define NCHUNK  (KCODES / CN)
#define KS      64      // dims per stage (B tiles)
#define NST     (DIM / KS)   // 4
#define NTHREADS 512
#define EPS     4e-3f

// smem layout (bytes):
// A persistent: 128 rows x 256 dims bf16 hi + lo (64KB each)
// B double-buffered: 128 codes x 64 dims bf16 hi + lo (16KB per buffer per region)
#define OFF_AH     0
#define OFF_AL     65536
#define OFF_BH     131072
#define OFF_BL     163840
#define OFF_SNORM  196608
#define OFF_SREDV  200704
#define OFF_SREDW  202752
#define OFF_SREDI  204800
#define OFF_SIDX   206848
#define SMEM_BYTES 207360
#define BBUF       16384

__device__ float g_enorm[KCODES];
__device__ int   g_nflag;
__device__ int   g_list[N_ROWS];

__device__ __forceinline__ uint32_t smem_u32(const void* p) {
    uint32_t a;
    asm("{ .reg .u64 t; cvta.to.shared.u64 t, %1; cvt.u32.u64 %0, t; }" : "=r"(a) : "l"(p));
    return a;
}

// float4 -> packed bf16 hi (uint2) + fp32 residual
__device__ __forceinline__ uint2 bfhi_pack(float4 v, float4& r) {
    uint2 h;
    asm("cvt.rn.bf16x2.f32 %0, %1, %2;" : "=r"(h.x) : "f"(v.y), "f"(v.x));
    asm("cvt.rn.bf16x2.f32 %0, %1, %2;" : "=r"(h.y) : "f"(v.w), "f"(v.z));
    r.x = v.x - __uint_as_float(h.x << 16);
    r.y = v.y - __uint_as_float(h.x & 0xffff0000u);
    r.z = v.z - __uint_as_float(h.y << 16);
    r.w = v.w - __uint_as_float(h.y & 0xffff0000u);
    return h;
}
__device__ __forceinline__ uint2 bflo_pack(float4 r) {
    uint2 l;
    asm("cvt.rn.bf16x2.f32 %0, %1, %2;" : "=r"(l.x) : "f"(r.y), "f"(r.x));
    asm("cvt.rn.bf16x2.f32 %0, %1, %2;" : "=r"(l.y) : "f"(r.w), "f"(r.z));
    return l;
}

__device__ __forceinline__ void ldm4(uint32_t* r, uint32_t addr) {
    asm volatile("ldmatrix.sync.aligned.m8n8.x4.shared.b16 {%0,%1,%2,%3}, [%4];"
                 : "=r"(r[0]), "=r"(r[1]), "=r"(r[2]), "=r"(r[3]) : "r"(addr));
}

__device__ __forceinline__ void mma16(float* c, const uint32_t* a, uint32_t b0, uint32_t b1) {
    asm volatile(
        "mma.sync.aligned.m16n8k16.row.col.f32.bf16.bf16.f32 "
        "{%0,%1,%2,%3}, {%4,%5,%6,%7}, {%8,%9}, {%0,%1,%2,%3};"
        : "+f"(c[0]), "+f"(c[1]), "+f"(c[2]), "+f"(c[3])
        : "r"(a[0]), "r"(a[1]), "r"(a[2]), "r"(a[3]), "r"(b0), "r"(b1));
}

__global__ void enorm_kernel(const float* __restrict__ cb) {
    int code = blockIdx.x;
    int t = threadIdx.x;  // 64 threads, one float4 each
    if (code == 0 && t == 0) g_nflag = 0;    // reset rescue list every replay
    const float4* row = reinterpret_cast<const float4*>(cb + (size_t)code * DIM);
    float4 v = row[t];
    float s = v.x * v.x + v.y * v.y + v.z * v.z + v.w * v.w;
    #pragma unroll
    for (int o = 16; o > 0; o >>= 1) s += __shfl_down_sync(0xffffffffu, s, o);
    __shared__ float ws[2];
    if ((t & 31) == 0) ws[t >> 5] = s;
    __syncthreads();
    if (t == 0) g_enorm[code] = ws[0] + ws[1];
}

__global__ __launch_bounds__(NTHREADS, 1)
void vq_kernel(const float* __restrict__ x, const float* __restrict__ cb,
               float* __restrict__ outq, float* __restrict__ outidx, int has_idx)
{
    extern __shared__ char sm[];
    const uint32_t sb = smem_u32(sm);
    const int tid  = threadIdx.x;
    const int lane = tid & 31;
    const int wid  = tid >> 5;       // 0..15
    const int wm   = wid & 3;        // rows wm*32..+31
    const int wn   = wid >> 2;       // codes wn*32..+31 within 128-code chunk
    const int r0   = blockIdx.x * RN;

    float* snorm = (float*)(sm + OFF_SNORM);
    for (int i = tid; i < KCODES; i += NTHREADS) snorm[i] = g_enorm[i];

    // ---- Phase 1: convert A (128 rows x 256 dims) once into persistent smem ----
    // A layout: tile(mb,kd) at (mb*32 + kd)*128 bytes; mb=row>>3 (0..15), kd=dimquad>>1 (0..31)
    // within tile: (row&7)*16 + (dimquad&1)*8
    #pragma unroll
    for (int i = 0; i < 16; i++) {
        const int f  = tid + i * NTHREADS;        // 0..8191 float4s
        const int row = f >> 6;                   // 64 float4 per row
        const int q   = f & 63;
        const float4 v = *(const float4*)(x + (size_t)(r0 + row) * DIM + q * 4);
        float4 r;
        const uint2 h = bfhi_pack(v, r);
        const uint2 l = bflo_pack(r);
        const uint32_t dA = (uint32_t)((((row >> 3) * 32) + (q >> 1)) * 128 + (row & 7) * 16 + (q & 1) * 8);
        *(uint2*)(sm + OFF_AH + dA) = h;
        *(uint2*)(sm + OFF_AL + dA) = l;
    }

    // B stage-load mapping: stage = 128 codes x 64 dims = 2048 float4, 4 per thread.
    // B layout: tile(nb,kb) at (nb*8 + kb)*128; nb=code>>3 (0..15), kb=dimquad>>1 (0..7)
    int   browi[4], bqi[4];
    uint32_t bdst[4];
    #pragma unroll
    for (int i = 0; i < 4; i++) {
        const int f = tid + i * NTHREADS;         // 0..2047
        browi[i] = f >> 4;                        // 16 float4 per 64-dim row
        bqi[i]   = f & 15;
        bdst[i]  = (uint32_t)((((browi[i] >> 3) * 8) + (bqi[i] >> 1)) * 128 + (browi[i] & 7) * 16 + (bqi[i] & 1) * 8);
    }

    // ldmatrix lane offsets
    // A: x4 tiles (m0k0),(m1k0),(m0k1),(m1k1): mb stride 4096, kd stride 128
    const uint32_t aoff = ((lane >> 3) & 1) * 4096 + (lane >> 4) * 128 + (lane & 7) * 16;
    // B: x4 tiles (n0k0),(n0k1),(n1k0),(n1k1): nb stride 1024, kb stride 128
    const uint32_t boff = ((lane >> 3) & 1) * 128 + (lane >> 4) * 1024 + (lane & 7) * 16;

    float minv[4], minw[4];
    int   mini[4];
    #pragma unroll
    for (int i = 0; i < 4; i++) { minv[i] = FLT_MAX; minw[i] = FLT_MAX; mini[i] = 0; }

    __syncthreads();   // A conversion complete

    #pragma unroll 1
    for (int c = 0; c < NCHUNK; c++) {
        const int cbase = c * CN;
        float acc[2][4][4];
        #pragma unroll
        for (int mt = 0; mt < 2; mt++)
            #pragma unroll
            for (int nt = 0; nt < 4; nt++)
                #pragma unroll
                for (int q = 0; q < 4; q++) acc[mt][nt][q] = 0.0f;

        if (c > 0) __syncthreads();   // previous chunk done with B tiles

        // --- B stage 0 load (dims 0..63) ---
        #pragma unroll
        for (int i = 0; i < 4; i++) {
            const float4 v = *(const float4*)(cb + (size_t)(cbase + browi[i]) * DIM + bqi[i] * 4);
            float4 r;
            const uint2 h = bfhi_pack(v, r);
            *(uint2*)(sm + OFF_BH + bdst[i]) = h;
            *(uint2*)(sm + OFF_BL + bdst[i]) = bflo_pack(r);
        }
        __syncthreads();

        int buf = 0;
        #pragma unroll 1
        for (int s = 0; s < NST; s++) {
            float4 pb[4];
            if (s < NST - 1) {
                const int dd = (s + 1) * KS;
                #pragma unroll
                for (int i = 0; i < 4; i++)
                    pb[i] = *(const float4*)(cb + (size_t)(cbase + browi[i]) * DIM + dd + bqi[i] * 4);
            }

            const uint32_t bhb = sb + OFF_BH + (uint32_t)buf * BBUF;
            const uint32_t blb = sb + OFF_BL + (uint32_t)buf * BBUF;
            const uint32_t ahb = sb + OFF_AH;
            const uint32_t alb = sb + OFF_AL;

            #pragma unroll
            for (int ks2 = 0; ks2 < 4; ks2++) {   // four k16 slices per 64-dim stage
                uint32_t ah[2][4], al[2][4], bh[2][4], bl[2][4];
                #pragma unroll
                for (int mt = 0; mt < 2; mt++) {
                    const uint32_t tb = (uint32_t)(((wm * 4 + mt * 2) * 32 + (s * 8 + ks2 * 2)) * 128);
                    ldm4(ah[mt], ahb + tb + aoff);
                    ldm4(al[mt], alb + tb + aoff);
                }
                #pragma unroll
                for (int np = 0; np < 2; np++) {
                    const uint32_t tb = (uint32_t)(((wn * 4 + np * 2) * 8 + ks2 * 2) * 128);
                    ldm4(bh[np], bhb + tb + boff);
                    ldm4(bl[np], blb + tb + boff);
                }
                // bf16x3: hh + hl + lh, product-major (revisit distance 8); order matches R14
                #pragma unroll
                for (int np = 0; np < 2; np++)
                    #pragma unroll
                    for (int mt = 0; mt < 2; mt++) {
                        mma16(acc[mt][np * 2],     ah[mt], bh[np][0], bh[np][1]);
                        mma16(acc[mt][np * 2 + 1], ah[mt], bh[np][2], bh[np][3]);
                    }
                #pragma unroll
                for (int np = 0; np < 2; np++)
                    #pragma unroll
                    for (int mt = 0; mt < 2; mt++) {
                        mma16(acc[mt][np * 2],     ah[mt], bl[np][0], bl[np][1]);
                        mma16(acc[mt][np * 2 + 1], ah[mt], bl[np][2], bl[np][3]);
                    }
                #pragma unroll
                for (int np = 0; np < 2; np++)
                    #pragma unroll
                    for (int mt = 0; mt < 2; mt++) {
                        mma16(acc[mt][np * 2],     al[mt], bh[np][0], bh[np][1]);
                        mma16(acc[mt][np * 2 + 1], al[mt], bh[np][2], bh[np][3]);
                    }
            }

            if (s < NST - 1) {
                const int nb = buf ^ 1;
                #pragma unroll
                for (int i = 0; i < 4; i++) {
                    float4 r;
                    const uint2 h = bfhi_pack(pb[i], r);
                    *(uint2*)(sm + OFF_BH + nb * BBUF + bdst[i]) = h;
                    *(uint2*)(sm + OFF_BL + nb * BBUF + bdst[i]) = bflo_pack(r);
                }
                __syncthreads();
                buf = nb;
            }
        }

        // --- chunk epilogue: dist = ||e||^2 - 2 x.e ; track best + second-best ---
        #pragma unroll
        for (int nt = 0; nt < 4; nt++) {
            const int code0 = cbase + wn * 32 + nt * 8 + 2 * (lane & 3);
            const float en0 = snorm[code0];
            const float en1 = snorm[code0 + 1];
            #pragma unroll
            for (int mt = 0; mt < 2; mt++) {
                const float* a = acc[mt][nt];
                const int s0 = mt * 2, s1 = mt * 2 + 1;
                float d;
                d = en0 - 2.0f * a[0];
                if (d < minv[s0]) { minw[s0] = minv[s0]; minv[s0] = d; mini[s0] = code0; }
                else if (d < minw[s0]) minw[s0] = d;
                d = en1 - 2.0f * a[1];
                if (d < minv[s0]) { minw[s0] = minv[s0]; minv[s0] = d; mini[s0] = code0 + 1; }
                else if (d < minw[s0]) minw[s0] = d;
                d = en0 - 2.0f * a[2];
                if (d < minv[s1]) { minw[s1] = minv[s1]; minv[s1] = d; mini[s1] = code0; }
                else if (d < minw[s1]) minw[s1] = d;
                d = en1 - 2.0f * a[3];
                if (d < minv[s1]) { minw[s1] = minv[s1]; minv[s1] = d; mini[s1] = code0 + 1; }
                else if (d < minw[s1]) minw[s1] = d;
            }
        }
    }

    // --- reduce (best, idx, second) across lane%4 group, then across 4 wn groups ---
    float* sredv = (float*)(sm + OFF_SREDV);
    float* sredw = (float*)(sm + OFF_SREDW);
    int*   sredi = (int*)(sm + OFF_SREDI);
    #pragma unroll
    for (int sl = 0; sl < 4; sl++) {
        float v = minv[sl], w = minw[sl];
        int   id = mini[sl];
        #pragma unroll
        for (int o = 1; o <= 2; o <<= 1) {
            const float ov = __shfl_xor_sync(0xffffffffu, v, o);
            const float ow = __shfl_xor_sync(0xffffffffu, w, o);
            const int   oi = __shfl_xor_sync(0xffffffffu, id, o);
            if (ov < v || (ov == v && oi < id)) { w = fminf(v, ow); v = ov; id = oi; }
            else                                 { w = fminf(ov, w); }
        }
        if ((lane & 3) == 0) {
            const int rowl = wm * 32 + (sl >> 1) * 16 + (sl & 1) * 8 + (lane >> 2);
            sredv[wn * 128 + rowl] = v;
            sredw[wn * 128 + rowl] = w;
            sredi[wn * 128 + rowl] = id;
        }
    }
    __syncthreads();
    int* sIdx = (int*)(sm + OFF_SIDX);
    if (tid < 128) {
        float v0 = sredv[tid], w0 = sredw[tid];
        int   i0 = sredi[tid];
        #pragma unroll
        for (int g = 1; g < 4; g++) {
            const float v1 = sredv[g * 128 + tid];
            const float w1 = sredw[g * 128 + tid];
            const int   i1 = sredi[g * 128 + tid];
            if (v1 < v0 || (v1 == v0 && i1 < i0)) { w0 = fminf(v0, w1); v0 = v1; i0 = i1; }
            else                                  { w0 = fminf(v1, w0); }
        }
        sIdx[tid] = i0;
        if (w0 - v0 < EPS) {
            const int p = atomicAdd(&g_nflag, 1);   // compacted rescue list
            g_list[p] = r0 + tid;
        }
    }
    __syncthreads();

    // --- gather e[idx] rows and write outputs ---
    const float4* cb4  = reinterpret_cast<const float4*>(cb);
    float4*       out4 = reinterpret_cast<float4*>(outq);
    #pragma unroll 4
    for (int f = tid; f < RN * DIM / 4; f += NTHREADS) {
        const int row  = f >> 6;
        const int cc   = f & 63;
        const int code = sIdx[row];
        out4[(size_t)(r0 + row) * (DIM / 4) + cc] = cb4[(size_t)code * (DIM / 4) + cc];
    }
    if (has_idx && tid < RN) outidx[r0 + tid] = (float)sIdx[tid];
}

// --- exact fp32 rescan for flagged rows (grid-strided over compacted list) ---
__global__ __launch_bounds__(256)
void rescan_kernel(const float* __restrict__ x, const float* __restrict__ cb,
                   float* __restrict__ outq, float* __restrict__ outidx, int has_idx)
{
    __shared__ float4 sx[DIM / 4];
    __shared__ float rv[256];
    __shared__ int   ri[256];
    const int tid = threadIdx.x;
    const int nflag = g_nflag;

    for (int it = blockIdx.x; it < nflag; it += gridDim.x) {
        const int row = g_list[it];
        if (tid < 64) sx[tid] = ((const float4*)(x + (size_t)row * DIM))[tid];
        __syncthreads();

        float best = FLT_MAX;
        int   bidx = 0;
        #pragma unroll 1
        for (int cc = 0; cc < 4; cc++) {
            const int code = tid + cc * 256;   // ascending per thread
            const float4* e4 = (const float4*)(cb + (size_t)code * DIM);
            float dot = 0.0f;
            #pragma unroll 8
            for (int i = 0; i < DIM / 4; i++) {
                const float4 ev = e4[i];
                const float4 xv = sx[i];
                dot = fmaf(xv.x, ev.x, dot);
                dot = fmaf(xv.y, ev.y, dot);
                dot = fmaf(xv.z, ev.z, dot);
                dot = fmaf(xv.w, ev.w, dot);
            }
            const float d = g_enorm[code] - 2.0f * dot;
            if (d < best) { best = d; bidx = code; }
        }
        rv[tid] = best; ri[tid] = bidx;
        __syncthreads();
        for (int o = 128; o > 0; o >>= 1) {
            if (tid < o) {
                const float v2 = rv[tid + o];
                const int   i2 = ri[tid + o];
                if (v2 < rv[tid] || (v2 == rv[tid] && i2 < ri[tid])) { rv[tid] = v2; ri[tid] = i2; }
            }
            __syncthreads();
        }
        const int widx = ri[0];
        if (tid < 64)
            ((float4*)(outq + (size_t)row * DIM))[tid] = ((const float4*)(cb + (size_t)widx * DIM))[tid];
        if (has_idx && tid == 0) outidx[row] = (float)widx;
        __syncthreads();
    }
}

extern "C" void kernel_launch(void* const* d_in, const int* in_sizes, int n_in,
                              void* d_out, int out_size) {
    const float* x  = (const float*)d_in[0];   // [65536, 256]
    const float* cb = (const float*)d_in[1];   // [1024, 256]
    float* outq = (float*)d_out;

    const int qElems = N_ROWS * DIM;
    const int has_idx = (out_size >= qElems + N_ROWS) ? 1 : 0;
    float* outidx = outq + qElems;

    cudaFuncSetAttribute(vq_kernel, cudaFuncAttributeMaxDynamicSharedMemorySize, SMEM_BYTES);

    enorm_kernel<<<KCODES, 64>>>(cb);
    vq_kernel<<<N_ROWS / RN, NTHREADS, SMEM_BYTES>>>(x, cb, outq, outidx, has_idx);
    rescan_kernel<<<1024, 256>>>(x, cb, outq, outidx, has_idx);
}